// round 2
// baseline (speedup 1.0000x reference)
#include <cuda_runtime.h>
#include <math.h>

// Problem constants
#define Bt  64
#define St  64
#define Ht  512
#define Et  512
#define Vt  8000
#define VHt 8512
#define Ft  1024          // [h | ctx]
#define Rt  4096          // B*S rows

// ---------------- device scratch (no mallocs allowed) ----------------
__device__ float g_U[Rt * Ht];        // 8 MB : U = emb[tok] @ W_ih^T + b_cell
__device__ float g_Wcat[Vt * Ft];     // 32 MB: [M1 | W_c2]
__device__ float g_bias[Vt];          // b_c + W_c1 @ b_ho
__device__ float g_F[Rt * Ft];        // 16 MB: per-(b,t) [h | ctx]
__device__ float g_WhhT[Ht * Ht];     // 1 MB : W_hh transposed (WhhT[k][i] = W_hh[i][k])

// ---------------- packed f32x2 helpers (Blackwell) ----------------
__device__ __forceinline__ unsigned long long pack1(float a) {
    unsigned int ai = __float_as_uint(a);
    unsigned long long r;
    asm("mov.b64 %0, {%1, %1};" : "=l"(r) : "r"(ai));
    return r;
}
__device__ __forceinline__ float2 unpack2(unsigned long long v) {
    unsigned int lo, hi;
    asm("mov.b64 {%0, %1}, %2;" : "=r"(lo), "=r"(hi) : "l"(v));
    return make_float2(__uint_as_float(lo), __uint_as_float(hi));
}
__device__ __forceinline__ void ffma2(unsigned long long& d,
                                      unsigned long long a,
                                      unsigned long long b) {
    asm("fma.rn.f32x2 %0, %1, %2, %0;" : "+l"(d) : "l"(a), "l"(b));
}

// ---------------- small prep kernels ----------------
__global__ void k_transpose(const float* __restrict__ W) {
    __shared__ float tile[32][33];
    int x = blockIdx.x * 32 + threadIdx.x;
    int y = blockIdx.y * 32 + threadIdx.y;
    tile[threadIdx.y][threadIdx.x] = W[y * Ht + x];
    __syncthreads();
    int ox = blockIdx.y * 32 + threadIdx.x;
    int oy = blockIdx.x * 32 + threadIdx.y;
    g_WhhT[oy * Ht + ox] = tile[threadIdx.x][threadIdx.y];
}

__global__ void k_wcat_tail(const float* __restrict__ W_c) {
    int idx = blockIdx.x * blockDim.x + threadIdx.x;
    if (idx < Vt * Ht) {
        int v = idx >> 9;
        int j = idx & 511;
        g_Wcat[(size_t)v * Ft + 512 + j] = W_c[(size_t)v * VHt + Vt + j];
    }
}

__global__ void k_bias(const float* __restrict__ W_c,
                       const float* __restrict__ b_ho,
                       const float* __restrict__ b_c) {
    int v = blockIdx.x;
    const float* row = W_c + (size_t)v * VHt;
    float p = 0.f;
    for (int u = threadIdx.x; u < Vt; u += 256) p += row[u] * b_ho[u];
    __shared__ float sm[256];
    sm[threadIdx.x] = p;
    __syncthreads();
    for (int s = 128; s > 0; s >>= 1) {
        if (threadIdx.x < s) sm[threadIdx.x] += sm[threadIdx.x + s];
        __syncthreads();
    }
    if (threadIdx.x == 0) g_bias[v] = sm[0] + b_c[v];
}

// ---------------- generic tiled SGEMM (fp32, f32x2 inner) ----------------
// C[M,N] = act( A(MxK) * op(B) + bias ),  all row-major.
// TRANSB=1 : B is (N,K), C = A*B^T.   TRANSB=0 : B is (K,N), C = A*B.
// GATHER=1 : A row r -> emb row tok(r), tok = (r%64==0) ? 1 : tgt[r]
template <bool TRANSB, bool GATHER, bool DOTANH, bool HASBIAS>
__global__ void __launch_bounds__(256, 2)
k_sgemm(const float* __restrict__ A, const float* __restrict__ B,
        float* __restrict__ C, const float* __restrict__ bias,
        const int* __restrict__ tgt,
        int M, int N, int K, int lda, int ldb, int ldc) {
    const int BM = 128, BN = 128, BK = 16;
    __shared__ __align__(16) float As[BK][BM + 4];
    __shared__ __align__(16) float Bs[BK][BN + 4];

    int tid = threadIdx.x;
    int m0 = blockIdx.y * BM;
    int n0 = blockIdx.x * BN;

    unsigned long long acc[8][4];
#pragma unroll
    for (int i = 0; i < 8; i++)
#pragma unroll
        for (int j = 0; j < 4; j++) acc[i][j] = 0ull;

    int a_k = (tid & 3) * 4;
    int a_r = tid >> 2;
    int tx = tid & 15, ty = tid >> 4;

    for (int k0 = 0; k0 < K; k0 += BK) {
        // ---- load A tile (128 x 16), along-K float4 ----
#pragma unroll
        for (int p = 0; p < 2; p++) {
            int r  = a_r + p * 64;
            int gm = m0 + r;
            float4 v = make_float4(0.f, 0.f, 0.f, 0.f);
            if (gm < M) {
                const float* arow;
                if (GATHER) {
                    int t   = gm & 63;
                    int tok = (t == 0) ? 1 : tgt[gm];
                    arow = A + (size_t)tok * lda;
                } else {
                    arow = A + (size_t)gm * lda;
                }
                v = *(const float4*)(arow + k0 + a_k);
            }
            As[a_k + 0][r] = v.x;
            As[a_k + 1][r] = v.y;
            As[a_k + 2][r] = v.z;
            As[a_k + 3][r] = v.w;
        }
        // ---- load B tile ----
        if (TRANSB) {
#pragma unroll
            for (int p = 0; p < 2; p++) {
                int n  = a_r + p * 64;   // same pattern as A
                int gn = n0 + n;
                float4 v = make_float4(0.f, 0.f, 0.f, 0.f);
                if (gn < N) v = *(const float4*)(B + (size_t)gn * ldb + k0 + a_k);
                Bs[a_k + 0][n] = v.x;
                Bs[a_k + 1][n] = v.y;
                Bs[a_k + 2][n] = v.z;
                Bs[a_k + 3][n] = v.w;
            }
        } else {
            int b_n = (tid & 31) * 4;
            int b_k = tid >> 5;
#pragma unroll
            for (int p = 0; p < 2; p++) {
                int kk = b_k + p * 8;
                int gn = n0 + b_n;
                float4 v = make_float4(0.f, 0.f, 0.f, 0.f);
                if (gn + 3 < N) v = *(const float4*)(B + (size_t)(k0 + kk) * ldb + gn);
                *(float4*)&Bs[kk][b_n] = v;
            }
        }
        __syncthreads();
        // ---- compute 8x8 per thread, packed f32x2 ----
#pragma unroll
        for (int k = 0; k < BK; k++) {
            float4 aq0 = *(const float4*)&As[k][ty * 8];
            float4 aq1 = *(const float4*)&As[k][ty * 8 + 4];
            ulonglong2 bq0 = *(const ulonglong2*)&Bs[k][tx * 8];
            ulonglong2 bq1 = *(const ulonglong2*)&Bs[k][tx * 8 + 4];
            float ra[8] = {aq0.x, aq0.y, aq0.z, aq0.w, aq1.x, aq1.y, aq1.z, aq1.w};
#pragma unroll
            for (int i = 0; i < 8; i++) {
                unsigned long long pa = pack1(ra[i]);
                ffma2(acc[i][0], pa, bq0.x);
                ffma2(acc[i][1], pa, bq0.y);
                ffma2(acc[i][2], pa, bq1.x);
                ffma2(acc[i][3], pa, bq1.y);
            }
        }
        __syncthreads();
    }
    // ---- epilogue ----
#pragma unroll
    for (int i = 0; i < 8; i++) {
        int gm = m0 + ty * 8 + i;
        if (gm >= M) continue;
        size_t crow = (size_t)gm * ldc;
#pragma unroll
        for (int jj = 0; jj < 4; jj++) {
            float2 v = unpack2(acc[i][jj]);
            int gn = n0 + tx * 8 + jj * 2;
            if (gn < N) {
                float x = v.x;
                if (HASBIAS) x += bias[gn];
                if (DOTANH) x = tanhf(x);
                C[crow + gn] = x;
            }
            if (gn + 1 < N) {
                float x = v.y;
                if (HASBIAS) x += bias[gn + 1];
                if (DOTANH) x = tanhf(x);
                C[crow + gn + 1] = x;
            }
        }
    }
}

// ---------------- recurrence + attention (one CTA per batch element) ----------------
__global__ void k_recurrence(const float* __restrict__ enc_g) {
    extern __shared__ float sm[];
    float* enc = sm;                 // 64*512
    float* h   = sm + St * Ht;       // 512
    float* sc  = h + Ht;             // 64
    float* wts = sc + St;            // 64

    int b   = blockIdx.x;
    int tid = threadIdx.x;           // 512
    int lane = tid & 31, warp = tid >> 5;

    // cache encoder_hiddens[b] (128 KB)
    const float4* eg = (const float4*)(enc_g + (size_t)b * St * Ht);
    float4* es = (float4*)enc;
    for (int i = tid; i < St * Ht / 4; i += 512) es[i] = eg[i];
    __syncthreads();
    h[tid] = enc[(St - 1) * Ht + tid];   // h0 = encoder_hiddens[:, -1]
    __syncthreads();

    for (int t = 0; t < St; t++) {
        // h_new = tanh(U + W_hh @ h)
        float acc = g_U[((size_t)b * St + t) * Ht + tid];
        const float* wcol = g_WhhT + tid;
#pragma unroll 8
        for (int k = 0; k < Ht; k++) acc += wcol[(size_t)k * Ht] * h[k];
        float hn = tanhf(acc);
        __syncthreads();
        h[tid] = hn;
        __syncthreads();

        // scores[j] = enc[j] . h_new ; warp w handles j = w, w+16, w+32, w+48
#pragma unroll
        for (int jj = 0; jj < 4; jj++) {
            int j = warp + jj * 16;
            const float* er = enc + j * Ht;
            float s = 0.f;
#pragma unroll 4
            for (int c = lane; c < Ht; c += 32) s += er[c] * h[c];
#pragma unroll
            for (int o = 16; o; o >>= 1) s += __shfl_xor_sync(~0u, s, o);
            if (lane == 0) sc[j] = s;
        }
        __syncthreads();

        // softmax over 64 (warp 0)
        if (warp == 0) {
            float s0 = sc[lane], s1 = sc[lane + 32];
            float mx = fmaxf(s0, s1);
#pragma unroll
            for (int o = 16; o; o >>= 1) mx = fmaxf(mx, __shfl_xor_sync(~0u, mx, o));
            float e0 = expf(s0 - mx), e1 = expf(s1 - mx);
            float sum = e0 + e1;
#pragma unroll
            for (int o = 16; o; o >>= 1) sum += __shfl_xor_sync(~0u, sum, o);
            float inv = 1.f / sum;
            wts[lane] = e0 * inv;
            wts[lane + 32] = e1 * inv;
        }
        __syncthreads();

        // ctx = sum_j w[j] * enc[j]
        float c = 0.f;
#pragma unroll 8
        for (int j = 0; j < St; j++) c += wts[j] * enc[j * Ht + tid];

        size_t r = (size_t)b * St + t;
        g_F[r * Ft + tid]        = hn;
        g_F[r * Ft + 512 + tid]  = c;
    }
}

// ---------------- launch ----------------
extern "C" void kernel_launch(void* const* d_in, const int* in_sizes, int n_in,
                              void* d_out, int out_size) {
    const int*   target = (const int*)  d_in[0];
    const float* enc    = (const float*)d_in[1];
    const float* emb    = (const float*)d_in[2];
    const float* W_ih   = (const float*)d_in[3];
    const float* W_hh   = (const float*)d_in[4];
    const float* b_cell = (const float*)d_in[5];
    const float* W_ho   = (const float*)d_in[6];
    const float* b_ho   = (const float*)d_in[7];
    const float* W_c    = (const float*)d_in[8];
    const float* b_c    = (const float*)d_in[9];
    float* out = (float*)d_out;

    float *pU, *pWcat, *pF, *pBias;
    cudaGetSymbolAddress((void**)&pU,    g_U);
    cudaGetSymbolAddress((void**)&pWcat, g_Wcat);
    cudaGetSymbolAddress((void**)&pF,    g_F);
    cudaGetSymbolAddress((void**)&pBias, g_bias);

    const int REC_SMEM = (St * Ht + Ht + St + St) * 4;   // ~133.6 KB
    cudaFuncSetAttribute(k_recurrence,
                         cudaFuncAttributeMaxDynamicSharedMemorySize, REC_SMEM);

    // prep
    k_transpose<<<dim3(16, 16), dim3(32, 32)>>>(W_hh);
    k_wcat_tail<<<(Vt * Ht + 255) / 256, 256>>>(W_c);
    k_bias<<<Vt, 256>>>(W_c, b_ho, b_c);

    // U = emb[tok] @ W_ih^T + b_cell          (M=4096, N=512, K=512)  NT + gather
    k_sgemm<true, true, false, true><<<dim3(4, 32), 256>>>(
        emb, W_ih, pU, b_cell, target, Rt, Ht, Et, Et, Et, Ht);

    // M1 = W_c1 @ W_ho  -> Wcat[:, 0:512]     (M=8000, N=512, K=8000) NN
    k_sgemm<false, false, false, false><<<dim3(4, 63), 256>>>(
        W_c, W_ho, pWcat, nullptr, nullptr, Vt, Ht, Vt, VHt, Ht, Ft);

    // sequential recurrence + attention -> g_F
    k_recurrence<<<Bt, Ht, REC_SMEM>>>(enc);

    // out = tanh(F @ Wcat^T + bias)           (M=4096, N=8000, K=1024) NT
    k_sgemm<true, false, true, true><<<dim3(63, 32), 256>>>(
        pF, pWcat, out, pBias, nullptr, Rt, Vt, Ft, Ft, Ft, Vt);
}

// round 3
// speedup vs baseline: 1.7133x; 1.7133x over previous
#include <cuda_runtime.h>
#include <math.h>

// Problem constants
#define Bt  64
#define St  64
#define Ht  512
#define Et  512
#define Vt  8000
#define VHt 8512
#define Ft  1024          // [h | ctx]
#define Rt  4096          // B*S rows

// ---------------- device scratch (no mallocs allowed) ----------------
__device__ float g_U[Rt * Ht];        // 8 MB : U = emb[tok] @ W_ih^T + b_cell
__device__ float g_Wcat[Vt * Ft];     // 32 MB: [M1 | W_c2]
__device__ float g_bias[Vt];          // b_c + W_c1 @ b_ho
__device__ float g_F[Rt * Ft];        // 16 MB: per-(b,t) [h | ctx]
__device__ float g_WhhT[Ht * Ht];     // 1 MB : W_hh transposed

// ---------------- packed f32x2 helpers (fp32 path, kept for U GEMM) ----------------
__device__ __forceinline__ unsigned long long pack1(float a) {
    unsigned int ai = __float_as_uint(a);
    unsigned long long r;
    asm("mov.b64 %0, {%1, %1};" : "=l"(r) : "r"(ai));
    return r;
}
__device__ __forceinline__ float2 unpack2(unsigned long long v) {
    unsigned int lo, hi;
    asm("mov.b64 {%0, %1}, %2;" : "=r"(lo), "=r"(hi) : "l"(v));
    return make_float2(__uint_as_float(lo), __uint_as_float(hi));
}
__device__ __forceinline__ void ffma2(unsigned long long& d,
                                      unsigned long long a,
                                      unsigned long long b) {
    asm("fma.rn.f32x2 %0, %1, %2, %0;" : "+l"(d) : "l"(a), "l"(b));
}

// ---------------- small prep kernels ----------------
__global__ void k_transpose(const float* __restrict__ W) {
    __shared__ float tile[32][33];
    int x = blockIdx.x * 32 + threadIdx.x;
    int y = blockIdx.y * 32 + threadIdx.y;
    tile[threadIdx.y][threadIdx.x] = W[y * Ht + x];
    __syncthreads();
    int ox = blockIdx.y * 32 + threadIdx.x;
    int oy = blockIdx.x * 32 + threadIdx.y;
    g_WhhT[oy * Ht + ox] = tile[threadIdx.x][threadIdx.y];
}

__global__ void k_wcat_tail(const float* __restrict__ W_c) {
    int idx = blockIdx.x * blockDim.x + threadIdx.x;
    if (idx < Vt * Ht) {
        int v = idx >> 9;
        int j = idx & 511;
        g_Wcat[(size_t)v * Ft + 512 + j] = W_c[(size_t)v * VHt + Vt + j];
    }
}

__global__ void k_bias(const float* __restrict__ W_c,
                       const float* __restrict__ b_ho,
                       const float* __restrict__ b_c) {
    int v = blockIdx.x;
    const float* row = W_c + (size_t)v * VHt;
    float p = 0.f;
    for (int u = threadIdx.x; u < Vt; u += 256) p += row[u] * b_ho[u];
    __shared__ float sm[256];
    sm[threadIdx.x] = p;
    __syncthreads();
    for (int s = 128; s > 0; s >>= 1) {
        if (threadIdx.x < s) sm[threadIdx.x] += sm[threadIdx.x + s];
        __syncthreads();
    }
    if (threadIdx.x == 0) g_bias[v] = sm[0] + b_c[v];
}

// ---------------- fp32 SGEMM (kept only for the gathered U GEMM) ----------------
template <bool TRANSB, bool GATHER, bool DOTANH, bool HASBIAS>
__global__ void __launch_bounds__(256, 2)
k_sgemm(const float* __restrict__ A, const float* __restrict__ B,
        float* __restrict__ C, const float* __restrict__ bias,
        const int* __restrict__ tgt,
        int M, int N, int K, int lda, int ldb, int ldc) {
    const int BM = 128, BN = 128, BK = 16;
    __shared__ __align__(16) float As[BK][BM + 4];
    __shared__ __align__(16) float Bs[BK][BN + 4];

    int tid = threadIdx.x;
    int m0 = blockIdx.y * BM;
    int n0 = blockIdx.x * BN;

    unsigned long long acc[8][4];
#pragma unroll
    for (int i = 0; i < 8; i++)
#pragma unroll
        for (int j = 0; j < 4; j++) acc[i][j] = 0ull;

    int a_k = (tid & 3) * 4;
    int a_r = tid >> 2;
    int tx = tid & 15, ty = tid >> 4;

    for (int k0 = 0; k0 < K; k0 += BK) {
#pragma unroll
        for (int p = 0; p < 2; p++) {
            int r  = a_r + p * 64;
            int gm = m0 + r;
            float4 v = make_float4(0.f, 0.f, 0.f, 0.f);
            if (gm < M) {
                const float* arow;
                if (GATHER) {
                    int t   = gm & 63;
                    int tok = (t == 0) ? 1 : tgt[gm];
                    arow = A + (size_t)tok * lda;
                } else {
                    arow = A + (size_t)gm * lda;
                }
                v = *(const float4*)(arow + k0 + a_k);
            }
            As[a_k + 0][r] = v.x;
            As[a_k + 1][r] = v.y;
            As[a_k + 2][r] = v.z;
            As[a_k + 3][r] = v.w;
        }
        if (TRANSB) {
#pragma unroll
            for (int p = 0; p < 2; p++) {
                int n  = a_r + p * 64;
                int gn = n0 + n;
                float4 v = make_float4(0.f, 0.f, 0.f, 0.f);
                if (gn < N) v = *(const float4*)(B + (size_t)gn * ldb + k0 + a_k);
                Bs[a_k + 0][n] = v.x;
                Bs[a_k + 1][n] = v.y;
                Bs[a_k + 2][n] = v.z;
                Bs[a_k + 3][n] = v.w;
            }
        } else {
            int b_n = (tid & 31) * 4;
            int b_k = tid >> 5;
#pragma unroll
            for (int p = 0; p < 2; p++) {
                int kk = b_k + p * 8;
                int gn = n0 + b_n;
                float4 v = make_float4(0.f, 0.f, 0.f, 0.f);
                if (gn + 3 < N) v = *(const float4*)(B + (size_t)(k0 + kk) * ldb + gn);
                *(float4*)&Bs[kk][b_n] = v;
            }
        }
        __syncthreads();
#pragma unroll
        for (int k = 0; k < BK; k++) {
            float4 aq0 = *(const float4*)&As[k][ty * 8];
            float4 aq1 = *(const float4*)&As[k][ty * 8 + 4];
            ulonglong2 bq0 = *(const ulonglong2*)&Bs[k][tx * 8];
            ulonglong2 bq1 = *(const ulonglong2*)&Bs[k][tx * 8 + 4];
            float ra[8] = {aq0.x, aq0.y, aq0.z, aq0.w, aq1.x, aq1.y, aq1.z, aq1.w};
#pragma unroll
            for (int i = 0; i < 8; i++) {
                unsigned long long pa = pack1(ra[i]);
                ffma2(acc[i][0], pa, bq0.x);
                ffma2(acc[i][1], pa, bq0.y);
                ffma2(acc[i][2], pa, bq1.x);
                ffma2(acc[i][3], pa, bq1.y);
            }
        }
        __syncthreads();
    }
#pragma unroll
    for (int i = 0; i < 8; i++) {
        int gm = m0 + ty * 8 + i;
        if (gm >= M) continue;
        size_t crow = (size_t)gm * ldc;
#pragma unroll
        for (int jj = 0; jj < 4; jj++) {
            float2 v = unpack2(acc[i][jj]);
            int gn = n0 + tx * 8 + jj * 2;
            if (gn < N) {
                float x = v.x;
                if (HASBIAS) x += bias[gn];
                if (DOTANH) x = tanhf(x);
                C[crow + gn] = x;
            }
            if (gn + 1 < N) {
                float x = v.y;
                if (HASBIAS) x += bias[gn + 1];
                if (DOTANH) x = tanhf(x);
                C[crow + gn + 1] = x;
            }
        }
    }
}

// ================= TF32 tensor-core GEMM =================
// C[M,N] = act(A * op(B) + bias). TRANSB=1: B is (N,K) row-major -> C = A*B^T.
//                                 TRANSB=0: B is (K,N) row-major -> C = A*B.
// 128x128 CTA tile, BK=32, cp.async double buffered, 8 warps of 64x32.
#define TBM 128
#define TBN 128
#define TBK 32
#define ASTR (TBK + 4)     // 36: As[m][36], conflict-free ((4m+k)%32 distinct)
#define BSTR_N (TBN + 8)   // 136: Bs[k][136], conflict-free ((8k+n)%32 distinct)

__device__ __forceinline__ void cpa16(float* dst, const float* src, bool p) {
    unsigned d = (unsigned)__cvta_generic_to_shared(dst);
    int sz = p ? 16 : 0;
    asm volatile("cp.async.cg.shared.global [%0], [%1], 16, %2;\n"
                 :: "r"(d), "l"(src), "r"(sz));
}
__device__ __forceinline__ void cp_commit() { asm volatile("cp.async.commit_group;\n"); }
__device__ __forceinline__ void cp_wait0()  { asm volatile("cp.async.wait_group 0;\n"); }

__device__ __forceinline__ unsigned cvt_tf32(float x) {
    unsigned r;
    asm("cvt.rna.tf32.f32 %0, %1;" : "=r"(r) : "f"(x));
    return r;
}
__device__ __forceinline__ void mma_tf32(float* c, const unsigned* a, const unsigned* b) {
    asm volatile("mma.sync.aligned.m16n8k8.row.col.f32.tf32.tf32.f32 "
                 "{%0,%1,%2,%3}, {%4,%5,%6,%7}, {%8,%9}, {%0,%1,%2,%3};\n"
                 : "+f"(c[0]), "+f"(c[1]), "+f"(c[2]), "+f"(c[3])
                 : "r"(a[0]), "r"(a[1]), "r"(a[2]), "r"(a[3]), "r"(b[0]), "r"(b[1]));
}

template <bool TRANSB, bool DOTANH, bool HASBIAS>
__global__ void __launch_bounds__(256, 2)
k_tgemm(const float* __restrict__ A, const float* __restrict__ B,
        float* __restrict__ C, const float* __restrict__ bias,
        int M, int N, int K, int lda, int ldb, int ldc) {
    extern __shared__ float smem[];
    float (*As)[TBM][ASTR] = (float(*)[TBM][ASTR])smem;          // 2 x 128 x 36
    float* bbase = smem + 2 * TBM * ASTR;

    int tid  = threadIdx.x;
    int lane = tid & 31, warp = tid >> 5;
    int l4 = lane >> 2, l2 = lane & 3;
    int wm = warp & 1, wn = warp >> 1;        // 2 warps (M) x 4 warps (N)
    int m0 = blockIdx.y * TBM, n0 = blockIdx.x * TBN;
    int m0w = wm * 64, n0w = wn * 32;

    float acc[4][4][4];
#pragma unroll
    for (int i = 0; i < 4; i++)
#pragma unroll
        for (int j = 0; j < 4; j++)
#pragma unroll
            for (int q = 0; q < 4; q++) acc[i][j][q] = 0.f;

    const int KT = K / TBK;                   // K is a multiple of 32 here

    auto load_tile = [&](int kt, int buf) {
        int k0 = kt * TBK;
        // A tile: 128 rows x 32 floats = 1024 16B chunks -> 4 per thread
#pragma unroll
        for (int i = 0; i < 4; i++) {
            int ch = tid + i * 256;
            int r = ch >> 3, c = (ch & 7) * 4;
            int gm = m0 + r;
            bool p = gm < M;
            const float* src = A + (size_t)(p ? gm : 0) * lda + k0 + c;
            cpa16(&As[buf][r][c], src, p);
        }
        if (TRANSB) {
            float (*Bs)[TBN][ASTR] = (float(*)[TBN][ASTR])bbase;
#pragma unroll
            for (int i = 0; i < 4; i++) {
                int ch = tid + i * 256;
                int r = ch >> 3, c = (ch & 7) * 4;
                int gn = n0 + r;
                bool p = gn < N;
                const float* src = B + (size_t)(p ? gn : 0) * ldb + k0 + c;
                cpa16(&Bs[buf][r][c], src, p);
            }
        } else {
            float (*Bs)[TBK][BSTR_N] = (float(*)[TBK][BSTR_N])bbase;
#pragma unroll
            for (int i = 0; i < 4; i++) {
                int ch = tid + i * 256;
                int r = ch >> 5, c = (ch & 31) * 4;
                int gn = n0 + c;
                bool p = (gn + 3) < N;
                const float* src = B + (size_t)(k0 + r) * ldb + (p ? gn : 0);
                cpa16(&Bs[buf][r][c], src, p);
            }
        }
        cp_commit();
    };

    auto compute = [&](int buf) {
#pragma unroll
        for (int ks = 0; ks < 4; ks++) {
            int kk = ks * 8;
            unsigned af[4][4];
#pragma unroll
            for (int mt = 0; mt < 4; mt++) {
                int rm = m0w + mt * 16 + l4;
                af[mt][0] = cvt_tf32(As[buf][rm][kk + l2]);
                af[mt][1] = cvt_tf32(As[buf][rm + 8][kk + l2]);
                af[mt][2] = cvt_tf32(As[buf][rm][kk + 4 + l2]);
                af[mt][3] = cvt_tf32(As[buf][rm + 8][kk + 4 + l2]);
            }
            unsigned bf[4][2];
            if (TRANSB) {
                float (*Bs)[TBN][ASTR] = (float(*)[TBN][ASTR])bbase;
#pragma unroll
                for (int nt = 0; nt < 4; nt++) {
                    int cn = n0w + nt * 8 + l4;
                    bf[nt][0] = cvt_tf32(Bs[buf][cn][kk + l2]);
                    bf[nt][1] = cvt_tf32(Bs[buf][cn][kk + 4 + l2]);
                }
            } else {
                float (*Bs)[TBK][BSTR_N] = (float(*)[TBK][BSTR_N])bbase;
#pragma unroll
                for (int nt = 0; nt < 4; nt++) {
                    int cn = n0w + nt * 8 + l4;
                    bf[nt][0] = cvt_tf32(Bs[buf][kk + l2][cn]);
                    bf[nt][1] = cvt_tf32(Bs[buf][kk + 4 + l2][cn]);
                }
            }
#pragma unroll
            for (int mt = 0; mt < 4; mt++)
#pragma unroll
                for (int nt = 0; nt < 4; nt++)
                    mma_tf32(acc[mt][nt], af[mt], bf[nt]);
        }
    };

    load_tile(0, 0);
    int buf = 0;
    for (int kt = 0; kt < KT; kt++) {
        cp_wait0();
        __syncthreads();
        if (kt + 1 < KT) load_tile(kt + 1, buf ^ 1);
        compute(buf);
        buf ^= 1;
    }

    // epilogue
#pragma unroll
    for (int mt = 0; mt < 4; mt++) {
        int r0 = m0 + m0w + mt * 16 + l4;
        int r1 = r0 + 8;
#pragma unroll
        for (int nt = 0; nt < 4; nt++) {
            int cc = n0 + n0w + nt * 8 + l2 * 2;
            if (cc >= N) continue;              // N even -> pair-safe
            float b0v = 0.f, b1v = 0.f;
            if (HASBIAS) { b0v = bias[cc]; b1v = bias[cc + 1]; }
            float* a = acc[mt][nt];
            if (r0 < M) {
                float x0 = a[0] + b0v, x1 = a[1] + b1v;
                if (DOTANH) { x0 = tanhf(x0); x1 = tanhf(x1); }
                *(float2*)(C + (size_t)r0 * ldc + cc) = make_float2(x0, x1);
            }
            if (r1 < M) {
                float x0 = a[2] + b0v, x1 = a[3] + b1v;
                if (DOTANH) { x0 = tanhf(x0); x1 = tanhf(x1); }
                *(float2*)(C + (size_t)r1 * ldc + cc) = make_float2(x0, x1);
            }
        }
    }
}

// ---------------- recurrence + attention (one CTA per batch element) ----------------
__global__ void k_recurrence(const float* __restrict__ enc_g) {
    extern __shared__ float sm[];
    float* enc = sm;                 // 64*512
    float* h   = sm + St * Ht;       // 512
    float* sc  = h + Ht;             // 64
    float* wts = sc + St;            // 64

    int b   = blockIdx.x;
    int tid = threadIdx.x;           // 512
    int lane = tid & 31, warp = tid >> 5;

    const float4* eg = (const float4*)(enc_g + (size_t)b * St * Ht);
    float4* es = (float4*)enc;
    for (int i = tid; i < St * Ht / 4; i += 512) es[i] = eg[i];
    __syncthreads();
    h[tid] = enc[(St - 1) * Ht + tid];
    __syncthreads();

    for (int t = 0; t < St; t++) {
        float acc = g_U[((size_t)b * St + t) * Ht + tid];
        const float* wcol = g_WhhT + tid;
#pragma unroll 8
        for (int k = 0; k < Ht; k++) acc += wcol[(size_t)k * Ht] * h[k];
        float hn = tanhf(acc);
        __syncthreads();
        h[tid] = hn;
        __syncthreads();

#pragma unroll
        for (int jj = 0; jj < 4; jj++) {
            int j = warp + jj * 16;
            const float* er = enc + j * Ht;
            float s = 0.f;
#pragma unroll 4
            for (int c = lane; c < Ht; c += 32) s += er[c] * h[c];
#pragma unroll
            for (int o = 16; o; o >>= 1) s += __shfl_xor_sync(~0u, s, o);
            if (lane == 0) sc[j] = s;
        }
        __syncthreads();

        if (warp == 0) {
            float s0 = sc[lane], s1 = sc[lane + 32];
            float mx = fmaxf(s0, s1);
#pragma unroll
            for (int o = 16; o; o >>= 1) mx = fmaxf(mx, __shfl_xor_sync(~0u, mx, o));
            float e0 = expf(s0 - mx), e1 = expf(s1 - mx);
            float sum = e0 + e1;
#pragma unroll
            for (int o = 16; o; o >>= 1) sum += __shfl_xor_sync(~0u, sum, o);
            float inv = 1.f / sum;
            wts[lane] = e0 * inv;
            wts[lane + 32] = e1 * inv;
        }
        __syncthreads();

        float c = 0.f;
#pragma unroll 8
        for (int j = 0; j < St; j++) c += wts[j] * enc[j * Ht + tid];

        size_t r = (size_t)b * St + t;
        g_F[r * Ft + tid]        = hn;
        g_F[r * Ft + 512 + tid]  = c;
    }
}

// ---------------- launch ----------------
extern "C" void kernel_launch(void* const* d_in, const int* in_sizes, int n_in,
                              void* d_out, int out_size) {
    const int*   target = (const int*)  d_in[0];
    const float* enc    = (const float*)d_in[1];
    const float* emb    = (const float*)d_in[2];
    const float* W_ih   = (const float*)d_in[3];
    const float* W_hh   = (const float*)d_in[4];
    const float* b_cell = (const float*)d_in[5];
    const float* W_ho   = (const float*)d_in[6];
    const float* b_ho   = (const float*)d_in[7];
    const float* W_c    = (const float*)d_in[8];
    const float* b_c    = (const float*)d_in[9];
    float* out = (float*)d_out;

    float *pU, *pWcat, *pF, *pBias;
    cudaGetSymbolAddress((void**)&pU,    g_U);
    cudaGetSymbolAddress((void**)&pWcat, g_Wcat);
    cudaGetSymbolAddress((void**)&pF,    g_F);
    cudaGetSymbolAddress((void**)&pBias, g_bias);

    const int REC_SMEM = (St * Ht + Ht + St + St) * 4;   // ~133.6 KB
    cudaFuncSetAttribute(k_recurrence,
                         cudaFuncAttributeMaxDynamicSharedMemorySize, REC_SMEM);

    const int SMEM_NN = (2 * TBM * ASTR + 2 * TBK * BSTR_N) * 4;   // 71680
    const int SMEM_NT = (2 * TBM * ASTR + 2 * TBN * ASTR) * 4;     // 73728
    cudaFuncSetAttribute(k_tgemm<false, false, false>,
                         cudaFuncAttributeMaxDynamicSharedMemorySize, SMEM_NN);
    cudaFuncSetAttribute(k_tgemm<true, true, true>,
                         cudaFuncAttributeMaxDynamicSharedMemorySize, SMEM_NT);

    // prep
    k_transpose<<<dim3(16, 16), dim3(32, 32)>>>(W_hh);
    k_wcat_tail<<<(Vt * Ht + 255) / 256, 256>>>(W_c);
    k_bias<<<Vt, 256>>>(W_c, b_ho, b_c);

    // U = emb[tok] @ W_ih^T + b_cell          (M=4096, N=512, K=512)  fp32 NT + gather
    k_sgemm<true, true, false, true><<<dim3(4, 32), 256>>>(
        emb, W_ih, pU, b_cell, target, Rt, Ht, Et, Et, Et, Ht);

    // M1 = W_c1 @ W_ho  -> Wcat[:, 0:512]     (M=8000, N=512, K=8000) tf32 NN
    k_tgemm<false, false, false><<<dim3(4, 63), 256, SMEM_NN>>>(
        W_c, W_ho, pWcat, nullptr, Vt, Ht, Vt, VHt, Ht, Ft);

    // sequential recurrence + attention -> g_F
    k_recurrence<<<Bt, Ht, REC_SMEM>>>(enc);

    // out = tanh(F @ Wcat^T + bias)           (M=4096, N=8000, K=1024) tf32 NT
    k_tgemm<true, true, true><<<dim3(63, 32), 256, SMEM_NT>>>(
        pF, pWcat, out, pBias, Rt, Vt, Ft, Ft, Ft, Vt);
}

// round 4
// speedup vs baseline: 1.7273x; 1.0082x over previous
#include <cuda_runtime.h>
#include <math.h>

// Problem constants
#define Bt  64
#define St  64
#define Ht  512
#define Et  512
#define Vt  8000
#define VHt 8512
#define Ft  1024          // [h | ctx]
#define Rt  4096          // B*S rows

// ---------------- device scratch (no mallocs allowed) ----------------
__device__ float g_U[Rt * Ht];        // 8 MB : U = emb[tok] @ W_ih^T + b_cell
__device__ float g_Wcat[Vt * Ft];     // 32 MB: [M1 | W_c2]
__device__ float g_bias[Vt];          // b_c + W_c1 @ b_ho
__device__ float g_F[Rt * Ft];        // 16 MB: per-(b,t) [h | ctx]
__device__ float g_WhhT[Ht * Ht];     // 1 MB : W_hh transposed

// ---------------- packed f32x2 helpers (fp32 path, kept for U GEMM) ----------------
__device__ __forceinline__ unsigned long long pack1(float a) {
    unsigned int ai = __float_as_uint(a);
    unsigned long long r;
    asm("mov.b64 %0, {%1, %1};" : "=l"(r) : "r"(ai));
    return r;
}
__device__ __forceinline__ float2 unpack2(unsigned long long v) {
    unsigned int lo, hi;
    asm("mov.b64 {%0, %1}, %2;" : "=r"(lo), "=r"(hi) : "l"(v));
    return make_float2(__uint_as_float(lo), __uint_as_float(hi));
}
__device__ __forceinline__ void ffma2(unsigned long long& d,
                                      unsigned long long a,
                                      unsigned long long b) {
    asm("fma.rn.f32x2 %0, %1, %2, %0;" : "+l"(d) : "l"(a), "l"(b));
}

// ---------------- small prep kernels ----------------
__global__ void k_transpose(const float* __restrict__ W) {
    __shared__ float tile[32][33];
    int x = blockIdx.x * 32 + threadIdx.x;
    int y = blockIdx.y * 32 + threadIdx.y;
    tile[threadIdx.y][threadIdx.x] = W[y * Ht + x];
    __syncthreads();
    int ox = blockIdx.y * 32 + threadIdx.x;
    int oy = blockIdx.x * 32 + threadIdx.y;
    g_WhhT[oy * Ht + ox] = tile[threadIdx.x][threadIdx.y];
}

__global__ void k_wcat_tail(const float* __restrict__ W_c) {
    int idx = blockIdx.x * blockDim.x + threadIdx.x;
    if (idx < Vt * Ht) {
        int v = idx >> 9;
        int j = idx & 511;
        g_Wcat[(size_t)v * Ft + 512 + j] = W_c[(size_t)v * VHt + Vt + j];
    }
}

__global__ void k_bias(const float* __restrict__ W_c,
                       const float* __restrict__ b_ho,
                       const float* __restrict__ b_c) {
    int v = blockIdx.x;
    const float* row = W_c + (size_t)v * VHt;
    float p = 0.f;
    for (int u = threadIdx.x; u < Vt; u += 256) p += row[u] * b_ho[u];
    __shared__ float sm[256];
    sm[threadIdx.x] = p;
    __syncthreads();
    for (int s = 128; s > 0; s >>= 1) {
        if (threadIdx.x < s) sm[threadIdx.x] += sm[threadIdx.x + s];
        __syncthreads();
    }
    if (threadIdx.x == 0) g_bias[v] = sm[0] + b_c[v];
}

// ---------------- fp32 SGEMM (kept only for the gathered U GEMM) ----------------
template <bool TRANSB, bool GATHER, bool DOTANH, bool HASBIAS>
__global__ void __launch_bounds__(256, 2)
k_sgemm(const float* __restrict__ A, const float* __restrict__ B,
        float* __restrict__ C, const float* __restrict__ bias,
        const int* __restrict__ tgt,
        int M, int N, int K, int lda, int ldb, int ldc) {
    const int BM = 128, BN = 128, BK = 16;
    __shared__ __align__(16) float As[BK][BM + 4];
    __shared__ __align__(16) float Bs[BK][BN + 4];

    int tid = threadIdx.x;
    int m0 = blockIdx.y * BM;
    int n0 = blockIdx.x * BN;

    unsigned long long acc[8][4];
#pragma unroll
    for (int i = 0; i < 8; i++)
#pragma unroll
        for (int j = 0; j < 4; j++) acc[i][j] = 0ull;

    int a_k = (tid & 3) * 4;
    int a_r = tid >> 2;
    int tx = tid & 15, ty = tid >> 4;

    for (int k0 = 0; k0 < K; k0 += BK) {
#pragma unroll
        for (int p = 0; p < 2; p++) {
            int r  = a_r + p * 64;
            int gm = m0 + r;
            float4 v = make_float4(0.f, 0.f, 0.f, 0.f);
            if (gm < M) {
                const float* arow;
                if (GATHER) {
                    int t   = gm & 63;
                    int tok = (t == 0) ? 1 : tgt[gm];
                    arow = A + (size_t)tok * lda;
                } else {
                    arow = A + (size_t)gm * lda;
                }
                v = *(const float4*)(arow + k0 + a_k);
            }
            As[a_k + 0][r] = v.x;
            As[a_k + 1][r] = v.y;
            As[a_k + 2][r] = v.z;
            As[a_k + 3][r] = v.w;
        }
        if (TRANSB) {
#pragma unroll
            for (int p = 0; p < 2; p++) {
                int n  = a_r + p * 64;
                int gn = n0 + n;
                float4 v = make_float4(0.f, 0.f, 0.f, 0.f);
                if (gn < N) v = *(const float4*)(B + (size_t)gn * ldb + k0 + a_k);
                Bs[a_k + 0][n] = v.x;
                Bs[a_k + 1][n] = v.y;
                Bs[a_k + 2][n] = v.z;
                Bs[a_k + 3][n] = v.w;
            }
        } else {
            int b_n = (tid & 31) * 4;
            int b_k = tid >> 5;
#pragma unroll
            for (int p = 0; p < 2; p++) {
                int kk = b_k + p * 8;
                int gn = n0 + b_n;
                float4 v = make_float4(0.f, 0.f, 0.f, 0.f);
                if (gn + 3 < N) v = *(const float4*)(B + (size_t)(k0 + kk) * ldb + gn);
                *(float4*)&Bs[kk][b_n] = v;
            }
        }
        __syncthreads();
#pragma unroll
        for (int k = 0; k < BK; k++) {
            float4 aq0 = *(const float4*)&As[k][ty * 8];
            float4 aq1 = *(const float4*)&As[k][ty * 8 + 4];
            ulonglong2 bq0 = *(const ulonglong2*)&Bs[k][tx * 8];
            ulonglong2 bq1 = *(const ulonglong2*)&Bs[k][tx * 8 + 4];
            float ra[8] = {aq0.x, aq0.y, aq0.z, aq0.w, aq1.x, aq1.y, aq1.z, aq1.w};
#pragma unroll
            for (int i = 0; i < 8; i++) {
                unsigned long long pa = pack1(ra[i]);
                ffma2(acc[i][0], pa, bq0.x);
                ffma2(acc[i][1], pa, bq0.y);
                ffma2(acc[i][2], pa, bq1.x);
                ffma2(acc[i][3], pa, bq1.y);
            }
        }
        __syncthreads();
    }
#pragma unroll
    for (int i = 0; i < 8; i++) {
        int gm = m0 + ty * 8 + i;
        if (gm >= M) continue;
        size_t crow = (size_t)gm * ldc;
#pragma unroll
        for (int jj = 0; jj < 4; jj++) {
            float2 v = unpack2(acc[i][jj]);
            int gn = n0 + tx * 8 + jj * 2;
            if (gn < N) {
                float x = v.x;
                if (HASBIAS) x += bias[gn];
                if (DOTANH) x = tanhf(x);
                C[crow + gn] = x;
            }
            if (gn + 1 < N) {
                float x = v.y;
                if (HASBIAS) x += bias[gn + 1];
                if (DOTANH) x = tanhf(x);
                C[crow + gn + 1] = x;
            }
        }
    }
}

// ================= TF32 tensor-core GEMM =================
// C[M,N] = act(A * op(B) + bias). TRANSB=1: B is (N,K) row-major -> C = A*B^T.
//                                 TRANSB=0: B is (K,N) row-major -> C = A*B.
// 128x128 CTA tile, BK=32, cp.async double buffered, 8 warps of 64x32.
#define TBM 128
#define TBN 128
#define TBK 32
#define ASTR (TBK + 4)     // 36: As[m][36], conflict-free ((4m+k)%32 distinct)
#define BSTR_N (TBN + 8)   // 136: Bs[k][136], conflict-free ((8k+n)%32 distinct)

__device__ __forceinline__ void cpa16(float* dst, const float* src, bool p) {
    unsigned d = (unsigned)__cvta_generic_to_shared(dst);
    int sz = p ? 16 : 0;
    asm volatile("cp.async.cg.shared.global [%0], [%1], 16, %2;\n"
                 :: "r"(d), "l"(src), "r"(sz));
}
__device__ __forceinline__ void cp_commit() { asm volatile("cp.async.commit_group;\n"); }
__device__ __forceinline__ void cp_wait0()  { asm volatile("cp.async.wait_group 0;\n"); }

__device__ __forceinline__ unsigned cvt_tf32(float x) {
    unsigned r;
    asm("cvt.rna.tf32.f32 %0, %1;" : "=r"(r) : "f"(x));
    return r;
}
__device__ __forceinline__ void mma_tf32(float* c, const unsigned* a, const unsigned* b) {
    asm volatile("mma.sync.aligned.m16n8k8.row.col.f32.tf32.tf32.f32 "
                 "{%0,%1,%2,%3}, {%4,%5,%6,%7}, {%8,%9}, {%0,%1,%2,%3};\n"
                 : "+f"(c[0]), "+f"(c[1]), "+f"(c[2]), "+f"(c[3])
                 : "r"(a[0]), "r"(a[1]), "r"(a[2]), "r"(a[3]), "r"(b[0]), "r"(b[1]));
}

template <bool TRANSB, bool DOTANH, bool HASBIAS>
__global__ void __launch_bounds__(256, 2)
k_tgemm(const float* __restrict__ A, const float* __restrict__ B,
        float* __restrict__ C, const float* __restrict__ bias,
        int M, int N, int K, int lda, int ldb, int ldc) {
    extern __shared__ float smem[];
    float (*As)[TBM][ASTR] = (float(*)[TBM][ASTR])smem;          // 2 x 128 x 36
    float* bbase = smem + 2 * TBM * ASTR;

    int tid  = threadIdx.x;
    int lane = tid & 31, warp = tid >> 5;
    int l4 = lane >> 2, l2 = lane & 3;
    int wm = warp & 1, wn = warp >> 1;        // 2 warps (M) x 4 warps (N)
    int m0 = blockIdx.y * TBM, n0 = blockIdx.x * TBN;
    int m0w = wm * 64, n0w = wn * 32;

    float acc[4][4][4];
#pragma unroll
    for (int i = 0; i < 4; i++)
#pragma unroll
        for (int j = 0; j < 4; j++)
#pragma unroll
            for (int q = 0; q < 4; q++) acc[i][j][q] = 0.f;

    const int KT = K / TBK;                   // K is a multiple of 32 here

    auto load_tile = [&](int kt, int buf) {
        int k0 = kt * TBK;
        // A tile: 128 rows x 32 floats = 1024 16B chunks -> 4 per thread
#pragma unroll
        for (int i = 0; i < 4; i++) {
            int ch = tid + i * 256;
            int r = ch >> 3, c = (ch & 7) * 4;
            int gm = m0 + r;
            bool p = gm < M;
            const float* src = A + (size_t)(p ? gm : 0) * lda + k0 + c;
            cpa16(&As[buf][r][c], src, p);
        }
        if (TRANSB) {
            float (*Bs)[TBN][ASTR] = (float(*)[TBN][ASTR])bbase;
#pragma unroll
            for (int i = 0; i < 4; i++) {
                int ch = tid + i * 256;
                int r = ch >> 3, c = (ch & 7) * 4;
                int gn = n0 + r;
                bool p = gn < N;
                const float* src = B + (size_t)(p ? gn : 0) * ldb + k0 + c;
                cpa16(&Bs[buf][r][c], src, p);
            }
        } else {
            float (*Bs)[TBK][BSTR_N] = (float(*)[TBK][BSTR_N])bbase;
#pragma unroll
            for (int i = 0; i < 4; i++) {
                int ch = tid + i * 256;
                int r = ch >> 5, c = (ch & 31) * 4;
                int gn = n0 + c;
                bool p = (gn + 3) < N;
                const float* src = B + (size_t)(k0 + r) * ldb + (p ? gn : 0);
                cpa16(&Bs[buf][r][c], src, p);
            }
        }
        cp_commit();
    };

    auto compute = [&](int buf) {
#pragma unroll
        for (int ks = 0; ks < 4; ks++) {
            int kk = ks * 8;
            unsigned af[4][4];
#pragma unroll
            for (int mt = 0; mt < 4; mt++) {
                int rm = m0w + mt * 16 + l4;
                af[mt][0] = cvt_tf32(As[buf][rm][kk + l2]);
                af[mt][1] = cvt_tf32(As[buf][rm + 8][kk + l2]);
                af[mt][2] = cvt_tf32(As[buf][rm][kk + 4 + l2]);
                af[mt][3] = cvt_tf32(As[buf][rm + 8][kk + 4 + l2]);
            }
            unsigned bf[4][2];
            if (TRANSB) {
                float (*Bs)[TBN][ASTR] = (float(*)[TBN][ASTR])bbase;
#pragma unroll
                for (int nt = 0; nt < 4; nt++) {
                    int cn = n0w + nt * 8 + l4;
                    bf[nt][0] = cvt_tf32(Bs[buf][cn][kk + l2]);
                    bf[nt][1] = cvt_tf32(Bs[buf][cn][kk + 4 + l2]);
                }
            } else {
                float (*Bs)[TBK][BSTR_N] = (float(*)[TBK][BSTR_N])bbase;
#pragma unroll
                for (int nt = 0; nt < 4; nt++) {
                    int cn = n0w + nt * 8 + l4;
                    bf[nt][0] = cvt_tf32(Bs[buf][kk + l2][cn]);
                    bf[nt][1] = cvt_tf32(Bs[buf][kk + 4 + l2][cn]);
                }
            }
#pragma unroll
            for (int mt = 0; mt < 4; mt++)
#pragma unroll
                for (int nt = 0; nt < 4; nt++)
                    mma_tf32(acc[mt][nt], af[mt], bf[nt]);
        }
    };

    load_tile(0, 0);
    int buf = 0;
    for (int kt = 0; kt < KT; kt++) {
        cp_wait0();
        __syncthreads();
        if (kt + 1 < KT) load_tile(kt + 1, buf ^ 1);
        compute(buf);
        buf ^= 1;
    }

    // epilogue
#pragma unroll
    for (int mt = 0; mt < 4; mt++) {
        int r0 = m0 + m0w + mt * 16 + l4;
        int r1 = r0 + 8;
#pragma unroll
        for (int nt = 0; nt < 4; nt++) {
            int cc = n0 + n0w + nt * 8 + l2 * 2;
            if (cc >= N) continue;              // N even -> pair-safe
            float b0v = 0.f, b1v = 0.f;
            if (HASBIAS) { b0v = bias[cc]; b1v = bias[cc + 1]; }
            float* a = acc[mt][nt];
            if (r0 < M) {
                float x0 = a[0] + b0v, x1 = a[1] + b1v;
                if (DOTANH) { x0 = tanhf(x0); x1 = tanhf(x1); }
                *(float2*)(C + (size_t)r0 * ldc + cc) = make_float2(x0, x1);
            }
            if (r1 < M) {
                float x0 = a[2] + b0v, x1 = a[3] + b1v;
                if (DOTANH) { x0 = tanhf(x0); x1 = tanhf(x1); }
                *(float2*)(C + (size_t)r1 * ldc + cc) = make_float2(x0, x1);
            }
        }
    }
}

// ---------------- recurrence + attention (one CTA per batch element) ----------------
__global__ void k_recurrence(const float* __restrict__ enc_g) {
    extern __shared__ float sm[];
    float* enc = sm;                 // 64*512
    float* h   = sm + St * Ht;       // 512
    float* sc  = h + Ht;             // 64
    float* wts = sc + St;            // 64

    int b   = blockIdx.x;
    int tid = threadIdx.x;           // 512
    int lane = tid & 31, warp = tid >> 5;

    const float4* eg = (const float4*)(enc_g + (size_t)b * St * Ht);
    float4* es = (float4*)enc;
    for (int i = tid; i < St * Ht / 4; i += 512) es[i] = eg[i];
    __syncthreads();
    h[tid] = enc[(St - 1) * Ht + tid];
    __syncthreads();

    for (int t = 0; t < St; t++) {
        float acc = g_U[((size_t)b * St + t) * Ht + tid];
        const float* wcol = g_WhhT + tid;
#pragma unroll 8
        for (int k = 0; k < Ht; k++) acc += wcol[(size_t)k * Ht] * h[k];
        float hn = tanhf(acc);
        __syncthreads();
        h[tid] = hn;
        __syncthreads();

#pragma unroll
        for (int jj = 0; jj < 4; jj++) {
            int j = warp + jj * 16;
            const float* er = enc + j * Ht;
            float s = 0.f;
#pragma unroll 4
            for (int c = lane; c < Ht; c += 32) s += er[c] * h[c];
#pragma unroll
            for (int o = 16; o; o >>= 1) s += __shfl_xor_sync(~0u, s, o);
            if (lane == 0) sc[j] = s;
        }
        __syncthreads();

        if (warp == 0) {
            float s0 = sc[lane], s1 = sc[lane + 32];
            float mx = fmaxf(s0, s1);
#pragma unroll
            for (int o = 16; o; o >>= 1) mx = fmaxf(mx, __shfl_xor_sync(~0u, mx, o));
            float e0 = expf(s0 - mx), e1 = expf(s1 - mx);
            float sum = e0 + e1;
#pragma unroll
            for (int o = 16; o; o >>= 1) sum += __shfl_xor_sync(~0u, sum, o);
            float inv = 1.f / sum;
            wts[lane] = e0 * inv;
            wts[lane + 32] = e1 * inv;
        }
        __syncthreads();

        float c = 0.f;
#pragma unroll 8
        for (int j = 0; j < St; j++) c += wts[j] * enc[j * Ht + tid];

        size_t r = (size_t)b * St + t;
        g_F[r * Ft + tid]        = hn;
        g_F[r * Ft + 512 + tid]  = c;
    }
}

// ---------------- launch ----------------
extern "C" void kernel_launch(void* const* d_in, const int* in_sizes, int n_in,
                              void* d_out, int out_size) {
    const int*   target = (const int*)  d_in[0];
    const float* enc    = (const float*)d_in[1];
    const float* emb    = (const float*)d_in[2];
    const float* W_ih   = (const float*)d_in[3];
    const float* W_hh   = (const float*)d_in[4];
    const float* b_cell = (const float*)d_in[5];
    const float* W_ho   = (const float*)d_in[6];
    const float* b_ho   = (const float*)d_in[7];
    const float* W_c    = (const float*)d_in[8];
    const float* b_c    = (const float*)d_in[9];
    float* out = (float*)d_out;

    float *pU, *pWcat, *pF, *pBias;
    cudaGetSymbolAddress((void**)&pU,    g_U);
    cudaGetSymbolAddress((void**)&pWcat, g_Wcat);
    cudaGetSymbolAddress((void**)&pF,    g_F);
    cudaGetSymbolAddress((void**)&pBias, g_bias);

    const int REC_SMEM = (St * Ht + Ht + St + St) * 4;   // ~133.6 KB
    cudaFuncSetAttribute(k_recurrence,
                         cudaFuncAttributeMaxDynamicSharedMemorySize, REC_SMEM);

    const int SMEM_NN = (2 * TBM * ASTR + 2 * TBK * BSTR_N) * 4;   // 71680
    const int SMEM_NT = (2 * TBM * ASTR + 2 * TBN * ASTR) * 4;     // 73728
    cudaFuncSetAttribute(k_tgemm<false, false, false>,
                         cudaFuncAttributeMaxDynamicSharedMemorySize, SMEM_NN);
    cudaFuncSetAttribute(k_tgemm<true, true, true>,
                         cudaFuncAttributeMaxDynamicSharedMemorySize, SMEM_NT);

    // prep
    k_transpose<<<dim3(16, 16), dim3(32, 32)>>>(W_hh);
    k_wcat_tail<<<(Vt * Ht + 255) / 256, 256>>>(W_c);
    k_bias<<<Vt, 256>>>(W_c, b_ho, b_c);

    // U = emb[tok] @ W_ih^T + b_cell          (M=4096, N=512, K=512)  fp32 NT + gather
    k_sgemm<true, true, false, true><<<dim3(4, 32), 256>>>(
        emb, W_ih, pU, b_cell, target, Rt, Ht, Et, Et, Et, Ht);

    // M1 = W_c1 @ W_ho  -> Wcat[:, 0:512]     (M=8000, N=512, K=8000) tf32 NN
    k_tgemm<false, false, false><<<dim3(4, 63), 256, SMEM_NN>>>(
        W_c, W_ho, pWcat, nullptr, Vt, Ht, Vt, VHt, Ht, Ft);

    // sequential recurrence + attention -> g_F
    k_recurrence<<<Bt, Ht, REC_SMEM>>>(enc);

    // out = tanh(F @ Wcat^T + bias)           (M=4096, N=8000, K=1024) tf32 NT
    k_tgemm<true, true, true><<<dim3(63, 32), 256, SMEM_NT>>>(
        pF, pWcat, out, pBias, Rt, Vt, Ft, Ft, Ft, Vt);
}

// round 5
// speedup vs baseline: 2.9080x; 1.6835x over previous
#include <cuda_runtime.h>
#include <math.h>

// Problem constants
#define Bt  64
#define St  64
#define Ht  512
#define Et  512
#define Vt  8000
#define VHt 8512
#define Ft  1024          // [h | ctx]
#define Rt  4096          // B*S rows

// ---------------- device scratch (no mallocs allowed) ----------------
__device__ float g_U[Rt * Ht];        // 8 MB : U = emb[tok] @ W_ih^T + b_cell
__device__ float g_Wcat[Vt * Ft];     // 32 MB: [M1 | W_c2]  (tf32-rounded)
__device__ float g_bias[Vt];          // b_c + W_c1 @ b_ho
__device__ float g_F[Rt * Ft];        // 16 MB: per-(b,t) [h | ctx] (tf32-rounded)
__device__ float g_WhhT[Ht * Ht];     // 1 MB : W_hh transposed
__device__ float g_Whor[Vt * Ht];     // 16 MB: W_ho tf32-rounded

// ---------------- tf32 helpers ----------------
__device__ __forceinline__ unsigned cvt_tf32(float x) {
    unsigned r;
    asm("cvt.rna.tf32.f32 %0, %1;" : "=r"(r) : "f"(x));
    return r;
}
__device__ __forceinline__ float tf32r(float x) {
    return __uint_as_float(cvt_tf32(x));
}
__device__ __forceinline__ void mma_tf32(float* c, const unsigned* a, const unsigned* b) {
    asm volatile("mma.sync.aligned.m16n8k8.row.col.f32.tf32.tf32.f32 "
                 "{%0,%1,%2,%3}, {%4,%5,%6,%7}, {%8,%9}, {%0,%1,%2,%3};\n"
                 : "+f"(c[0]), "+f"(c[1]), "+f"(c[2]), "+f"(c[3])
                 : "r"(a[0]), "r"(a[1]), "r"(a[2]), "r"(a[3]), "r"(b[0]), "r"(b[1]));
}

// ---------------- cp.async helpers ----------------
__device__ __forceinline__ void cpa16(float* dst, const float* src, bool p) {
    unsigned d = (unsigned)__cvta_generic_to_shared(dst);
    int sz = p ? 16 : 0;
    asm volatile("cp.async.cg.shared.global [%0], [%1], 16, %2;\n"
                 :: "r"(d), "l"(src), "r"(sz));
}
__device__ __forceinline__ void cp_commit() { asm volatile("cp.async.commit_group;\n"); }
template <int N>
__device__ __forceinline__ void cp_wait() {
    asm volatile("cp.async.wait_group %0;\n" :: "n"(N));
}

// ---------------- packed f32x2 helpers (fp32 U GEMM) ----------------
__device__ __forceinline__ unsigned long long pack1(float a) {
    unsigned int ai = __float_as_uint(a);
    unsigned long long r;
    asm("mov.b64 %0, {%1, %1};" : "=l"(r) : "r"(ai));
    return r;
}
__device__ __forceinline__ float2 unpack2(unsigned long long v) {
    unsigned int lo, hi;
    asm("mov.b64 {%0, %1}, %2;" : "=r"(lo), "=r"(hi) : "l"(v));
    return make_float2(__uint_as_float(lo), __uint_as_float(hi));
}
__device__ __forceinline__ void ffma2(unsigned long long& d,
                                      unsigned long long a,
                                      unsigned long long b) {
    asm("fma.rn.f32x2 %0, %1, %2, %0;" : "+l"(d) : "l"(a), "l"(b));
}

// ---------------- small prep kernels ----------------
__global__ void k_transpose(const float* __restrict__ W) {
    __shared__ float tile[32][33];
    int x = blockIdx.x * 32 + threadIdx.x;
    int y = blockIdx.y * 32 + threadIdx.y;
    tile[threadIdx.y][threadIdx.x] = W[y * Ht + x];
    __syncthreads();
    int ox = blockIdx.y * 32 + threadIdx.x;
    int oy = blockIdx.x * 32 + threadIdx.y;
    g_WhhT[oy * Ht + ox] = tile[threadIdx.x][threadIdx.y];
}

__global__ void k_wcat_tail(const float* __restrict__ W_c) {
    int idx = blockIdx.x * blockDim.x + threadIdx.x;
    if (idx < Vt * Ht) {
        int v = idx >> 9;
        int j = idx & 511;
        g_Wcat[(size_t)v * Ft + 512 + j] = tf32r(W_c[(size_t)v * VHt + Vt + j]);
    }
}

__global__ void k_roundW(const float* __restrict__ W) {
    int idx = blockIdx.x * blockDim.x + threadIdx.x;
    if (idx < Vt * Ht) g_Whor[idx] = tf32r(W[idx]);
}

__global__ void k_bias(const float* __restrict__ W_c,
                       const float* __restrict__ b_ho,
                       const float* __restrict__ b_c) {
    int v = blockIdx.x;
    const float* row = W_c + (size_t)v * VHt;
    float p = 0.f;
    for (int u = threadIdx.x; u < Vt; u += 256) p += row[u] * b_ho[u];
    __shared__ float sm[256];
    sm[threadIdx.x] = p;
    __syncthreads();
    for (int s = 128; s > 0; s >>= 1) {
        if (threadIdx.x < s) sm[threadIdx.x] += sm[threadIdx.x + s];
        __syncthreads();
    }
    if (threadIdx.x == 0) g_bias[v] = sm[0] + b_c[v];
}

// ---------------- fp32 SGEMM (gathered U GEMM only) ----------------
template <bool TRANSB, bool GATHER, bool DOTANH, bool HASBIAS>
__global__ void __launch_bounds__(256, 2)
k_sgemm(const float* __restrict__ A, const float* __restrict__ B,
        float* __restrict__ C, const float* __restrict__ bias,
        const int* __restrict__ tgt,
        int M, int N, int K, int lda, int ldb, int ldc) {
    const int BM = 128, BN = 128, BK = 16;
    __shared__ __align__(16) float As[BK][BM + 4];
    __shared__ __align__(16) float Bs[BK][BN + 4];

    int tid = threadIdx.x;
    int m0 = blockIdx.y * BM;
    int n0 = blockIdx.x * BN;

    unsigned long long acc[8][4];
#pragma unroll
    for (int i = 0; i < 8; i++)
#pragma unroll
        for (int j = 0; j < 4; j++) acc[i][j] = 0ull;

    int a_k = (tid & 3) * 4;
    int a_r = tid >> 2;
    int tx = tid & 15, ty = tid >> 4;

    for (int k0 = 0; k0 < K; k0 += BK) {
#pragma unroll
        for (int p = 0; p < 2; p++) {
            int r  = a_r + p * 64;
            int gm = m0 + r;
            float4 v = make_float4(0.f, 0.f, 0.f, 0.f);
            if (gm < M) {
                const float* arow;
                if (GATHER) {
                    int t   = gm & 63;
                    int tok = (t == 0) ? 1 : tgt[gm];
                    arow = A + (size_t)tok * lda;
                } else {
                    arow = A + (size_t)gm * lda;
                }
                v = *(const float4*)(arow + k0 + a_k);
            }
            As[a_k + 0][r] = v.x;
            As[a_k + 1][r] = v.y;
            As[a_k + 2][r] = v.z;
            As[a_k + 3][r] = v.w;
        }
        {
#pragma unroll
            for (int p = 0; p < 2; p++) {
                int n  = a_r + p * 64;
                int gn = n0 + n;
                float4 v = make_float4(0.f, 0.f, 0.f, 0.f);
                if (gn < N) v = *(const float4*)(B + (size_t)gn * ldb + k0 + a_k);
                Bs[a_k + 0][n] = v.x;
                Bs[a_k + 1][n] = v.y;
                Bs[a_k + 2][n] = v.z;
                Bs[a_k + 3][n] = v.w;
            }
        }
        __syncthreads();
#pragma unroll
        for (int k = 0; k < BK; k++) {
            float4 aq0 = *(const float4*)&As[k][ty * 8];
            float4 aq1 = *(const float4*)&As[k][ty * 8 + 4];
            ulonglong2 bq0 = *(const ulonglong2*)&Bs[k][tx * 8];
            ulonglong2 bq1 = *(const ulonglong2*)&Bs[k][tx * 8 + 4];
            float ra[8] = {aq0.x, aq0.y, aq0.z, aq0.w, aq1.x, aq1.y, aq1.z, aq1.w};
#pragma unroll
            for (int i = 0; i < 8; i++) {
                unsigned long long pa = pack1(ra[i]);
                ffma2(acc[i][0], pa, bq0.x);
                ffma2(acc[i][1], pa, bq0.y);
                ffma2(acc[i][2], pa, bq1.x);
                ffma2(acc[i][3], pa, bq1.y);
            }
        }
        __syncthreads();
    }
#pragma unroll
    for (int i = 0; i < 8; i++) {
        int gm = m0 + ty * 8 + i;
        if (gm >= M) continue;
        size_t crow = (size_t)gm * ldc;
#pragma unroll
        for (int jj = 0; jj < 4; jj++) {
            float2 v = unpack2(acc[i][jj]);
            int gn = n0 + tx * 8 + jj * 2;
            if (gn < N) {
                float x = v.x;
                if (HASBIAS) x += bias[gn];
                if (DOTANH) x = tanhf(x);
                C[crow + gn] = x;
            }
            if (gn + 1 < N) {
                float x = v.y;
                if (HASBIAS) x += bias[gn + 1];
                if (DOTANH) x = tanhf(x);
                C[crow + gn + 1] = x;
            }
        }
    }
}

// ================= TF32 tensor-core GEMM v2 =================
// 128x256 CTA tile, BK=32, 3-stage cp.async, 8 warps of 64x64.
#define TBM 128
#define TBN 256
#define TBK 32
#define STG 3
#define ASTR 36        // As[m][36] / Bs_t[n][36]: (4m+k)%32 distinct -> conflict-free
#define BSTRN 264      // Bs_nn[k][264]: (8k+n)%32 distinct -> conflict-free

template <bool TRANSB, bool DOTANH, bool HASBIAS, bool CVTA, bool CVTB, bool ROUND>
__global__ void __launch_bounds__(256, 1)
k_tgemm2(const float* __restrict__ A, const float* __restrict__ B,
         float* __restrict__ C, const float* __restrict__ bias,
         int M, int N, int K, int lda, int ldb, int ldc) {
    extern __shared__ float smem[];
    float (*As)[TBM][ASTR] = (float(*)[TBM][ASTR])smem;      // STG x 128 x 36
    float* bb = smem + STG * TBM * ASTR;

    int tid  = threadIdx.x;
    int lane = tid & 31, warp = tid >> 5;
    int l4 = lane >> 2, l2 = lane & 3;
    int wm = warp & 1, wn = warp >> 1;          // 2 (M) x 4 (N)
    int m0 = blockIdx.y * TBM, n0 = blockIdx.x * TBN;
    int m0w = wm * 64, n0w = wn * 64;

    float acc[4][8][4];
#pragma unroll
    for (int i = 0; i < 4; i++)
#pragma unroll
        for (int j = 0; j < 8; j++)
#pragma unroll
            for (int q = 0; q < 4; q++) acc[i][j][q] = 0.f;

    const int KT = K / TBK;

    auto load_tile = [&](int kt, int buf) {
        int k0 = kt * TBK;
#pragma unroll
        for (int i = 0; i < 4; i++) {               // A: 128x32 = 1024 chunks
            int ch = tid + i * 256;
            int r = ch >> 3, c = (ch & 7) * 4;
            int gm = m0 + r;
            bool p = gm < M;
            cpa16(&As[buf][r][c], A + (size_t)(p ? gm : 0) * lda + k0 + c, p);
        }
        if (TRANSB) {
            float (*Bs)[TBN][ASTR] = (float(*)[TBN][ASTR])bb;
#pragma unroll
            for (int i = 0; i < 8; i++) {           // B: 256x32 = 2048 chunks
                int ch = tid + i * 256;
                int r = ch >> 3, c = (ch & 7) * 4;
                int gn = n0 + r;
                bool p = gn < N;
                cpa16(&Bs[buf][r][c], B + (size_t)(p ? gn : 0) * ldb + k0 + c, p);
            }
        } else {
            float (*Bs)[TBK][BSTRN] = (float(*)[TBK][BSTRN])bb;
#pragma unroll
            for (int i = 0; i < 8; i++) {           // B: 32x256 = 2048 chunks
                int ch = tid + i * 256;
                int r = ch >> 6, c = (ch & 63) * 4;
                int gn = n0 + c;
                bool p = (gn + 3) < N;
                cpa16(&Bs[buf][r][c], B + (size_t)(k0 + r) * ldb + (p ? gn : 0), p);
            }
        }
        cp_commit();
    };

    auto compute = [&](int buf) {
#pragma unroll
        for (int ks = 0; ks < 4; ks++) {
            int kk = ks * 8;
            unsigned af[4][4];
#pragma unroll
            for (int mt = 0; mt < 4; mt++) {
                int rm = m0w + mt * 16 + l4;
                float x0 = As[buf][rm][kk + l2];
                float x1 = As[buf][rm + 8][kk + l2];
                float x2 = As[buf][rm][kk + 4 + l2];
                float x3 = As[buf][rm + 8][kk + 4 + l2];
                af[mt][0] = CVTA ? cvt_tf32(x0) : __float_as_uint(x0);
                af[mt][1] = CVTA ? cvt_tf32(x1) : __float_as_uint(x1);
                af[mt][2] = CVTA ? cvt_tf32(x2) : __float_as_uint(x2);
                af[mt][3] = CVTA ? cvt_tf32(x3) : __float_as_uint(x3);
            }
            unsigned bf[8][2];
            if (TRANSB) {
                float (*Bs)[TBN][ASTR] = (float(*)[TBN][ASTR])bb;
#pragma unroll
                for (int nt = 0; nt < 8; nt++) {
                    int cn = n0w + nt * 8 + l4;
                    float y0 = Bs[buf][cn][kk + l2];
                    float y1 = Bs[buf][cn][kk + 4 + l2];
                    bf[nt][0] = CVTB ? cvt_tf32(y0) : __float_as_uint(y0);
                    bf[nt][1] = CVTB ? cvt_tf32(y1) : __float_as_uint(y1);
                }
            } else {
                float (*Bs)[TBK][BSTRN] = (float(*)[TBK][BSTRN])bb;
#pragma unroll
                for (int nt = 0; nt < 8; nt++) {
                    int cn = n0w + nt * 8 + l4;
                    float y0 = Bs[buf][kk + l2][cn];
                    float y1 = Bs[buf][kk + 4 + l2][cn];
                    bf[nt][0] = CVTB ? cvt_tf32(y0) : __float_as_uint(y0);
                    bf[nt][1] = CVTB ? cvt_tf32(y1) : __float_as_uint(y1);
                }
            }
#pragma unroll
            for (int mt = 0; mt < 4; mt++)
#pragma unroll
                for (int nt = 0; nt < 8; nt++)
                    mma_tf32(acc[mt][nt], af[mt], bf[nt]);
        }
    };

    load_tile(0, 0);
    load_tile(1, 1);
    for (int kt = 0; kt < KT; kt++) {
        cp_wait<1>();
        __syncthreads();
        int nx = kt + 2;
        if (nx < KT) load_tile(nx, nx % STG);
        compute(kt % STG);
    }

    // epilogue
#pragma unroll
    for (int mt = 0; mt < 4; mt++) {
        int r0 = m0 + m0w + mt * 16 + l4;
        int r1 = r0 + 8;
#pragma unroll
        for (int nt = 0; nt < 8; nt++) {
            int cc = n0 + n0w + nt * 8 + l2 * 2;
            if (cc >= N) continue;                 // N even -> pair-safe
            float b0 = 0.f, b1 = 0.f;
            if (HASBIAS) { b0 = bias[cc]; b1 = bias[cc + 1]; }
            float* a = acc[mt][nt];
            if (r0 < M) {
                float x0 = a[0] + b0, x1 = a[1] + b1;
                if (DOTANH) { x0 = tanhf(x0); x1 = tanhf(x1); }
                if (ROUND)  { x0 = tf32r(x0); x1 = tf32r(x1); }
                *(float2*)(C + (size_t)r0 * ldc + cc) = make_float2(x0, x1);
            }
            if (r1 < M) {
                float x0 = a[2] + b0, x1 = a[3] + b1;
                if (DOTANH) { x0 = tanhf(x0); x1 = tanhf(x1); }
                if (ROUND)  { x0 = tf32r(x0); x1 = tf32r(x1); }
                *(float2*)(C + (size_t)r1 * ldc + cc) = make_float2(x0, x1);
            }
        }
    }
}

// ---------------- recurrence + attention v2 (one CTA per batch element) -------
// Vectorized & coalesced: 4-way k-split; each thread owns a float4 of outputs.
__global__ void k_rec2(const float* __restrict__ enc_g) {
    extern __shared__ float sm[];
    float* enc = sm;                 // 64*512
    float* h   = enc + St * Ht;      // 512
    float* ps  = h + Ht;             // 4*512 partials
    float* sc  = ps + 4 * Ht;        // 64
    float* wts = sc + St;            // 64

    int b    = blockIdx.x;
    int tid  = threadIdx.x;          // 512
    int lane = tid & 31, warp = tid >> 5;
    int g4 = tid >> 7;               // k-group 0..3
    int it = tid & 127;
    int i4 = it * 4;                 // output quad base

    // cache encoder_hiddens[b] (128 KB)
    const float4* eg = (const float4*)(enc_g + (size_t)b * St * Ht);
    float4* es = (float4*)enc;
    for (int i = tid; i < St * Ht / 4; i += 512) es[i] = eg[i];
    __syncthreads();
    h[tid] = enc[(St - 1) * Ht + tid];
    __syncthreads();

    const float* wbase = g_WhhT + (size_t)(g4 * 128) * Ht + i4;
    const float* Urow0 = g_U + (size_t)b * St * Ht;

    for (int t = 0; t < St; t++) {
        // ---- matvec partial: rows k in [g4*128, g4*128+128) ----
        float4 a = make_float4(0.f, 0.f, 0.f, 0.f);
        const float* hb = h + g4 * 128;
#pragma unroll 4
        for (int kk = 0; kk < 128; kk++) {
            float hk = hb[kk];
            float4 w = *(const float4*)(wbase + (size_t)kk * Ht);
            a.x += w.x * hk; a.y += w.y * hk; a.z += w.z * hk; a.w += w.w * hk;
        }
        *(float4*)&ps[g4 * Ht + i4] = a;
        __syncthreads();
        float s = ps[tid] + ps[Ht + tid] + ps[2 * Ht + tid] + ps[3 * Ht + tid]
                + Urow0[(size_t)t * Ht + tid];
        float hn = tanhf(s);
        __syncthreads();
        h[tid] = hn;
        __syncthreads();

        // ---- scores: warp handles j = warp*4 .. warp*4+3 ----
#pragma unroll
        for (int jj = 0; jj < 4; jj++) {
            int j = warp * 4 + jj;
            const float4* er = (const float4*)(enc + j * Ht);
            const float4* hr = (const float4*)h;
            float sacc = 0.f;
#pragma unroll
            for (int p = 0; p < 4; p++) {
                float4 e  = er[p * 32 + lane];
                float4 hh = hr[p * 32 + lane];
                sacc += e.x * hh.x + e.y * hh.y + e.z * hh.z + e.w * hh.w;
            }
#pragma unroll
            for (int o = 16; o; o >>= 1) sacc += __shfl_xor_sync(~0u, sacc, o);
            if (lane == 0) sc[j] = sacc;
        }
        __syncthreads();

        // ---- softmax over 64 (warp 0) ----
        if (warp == 0) {
            float s0 = sc[lane], s1 = sc[lane + 32];
            float mx = fmaxf(s0, s1);
#pragma unroll
            for (int o = 16; o; o >>= 1) mx = fmaxf(mx, __shfl_xor_sync(~0u, mx, o));
            float e0 = expf(s0 - mx), e1 = expf(s1 - mx);
            float sum = e0 + e1;
#pragma unroll
            for (int o = 16; o; o >>= 1) sum += __shfl_xor_sync(~0u, sum, o);
            float inv = 1.f / sum;
            wts[lane] = e0 * inv;
            wts[lane + 32] = e1 * inv;
        }
        __syncthreads();

        // ---- ctx partial: j in [g4*16, g4*16+16) ----
        float4 c = make_float4(0.f, 0.f, 0.f, 0.f);
#pragma unroll
        for (int jj = 0; jj < 16; jj++) {
            int j = g4 * 16 + jj;
            float wj = wts[j];
            float4 e = *(const float4*)(enc + j * Ht + i4);
            c.x += e.x * wj; c.y += e.y * wj; c.z += e.z * wj; c.w += e.w * wj;
        }
        *(float4*)&ps[g4 * Ht + i4] = c;
        __syncthreads();
        float ctx = ps[tid] + ps[Ht + tid] + ps[2 * Ht + tid] + ps[3 * Ht + tid];

        size_t r = (size_t)b * St + t;
        g_F[r * Ft + tid]       = tf32r(hn);
        g_F[r * Ft + 512 + tid] = tf32r(ctx);
        __syncthreads();                       // ps reads done before next matvec
    }
}

// ---------------- launch ----------------
extern "C" void kernel_launch(void* const* d_in, const int* in_sizes, int n_in,
                              void* d_out, int out_size) {
    const int*   target = (const int*)  d_in[0];
    const float* enc    = (const float*)d_in[1];
    const float* emb    = (const float*)d_in[2];
    const float* W_ih   = (const float*)d_in[3];
    const float* W_hh   = (const float*)d_in[4];
    const float* b_cell = (const float*)d_in[5];
    const float* W_ho   = (const float*)d_in[6];
    const float* b_ho   = (const float*)d_in[7];
    const float* W_c    = (const float*)d_in[8];
    const float* b_c    = (const float*)d_in[9];
    float* out = (float*)d_out;

    float *pU, *pWcat, *pF, *pBias, *pWhor;
    cudaGetSymbolAddress((void**)&pU,    g_U);
    cudaGetSymbolAddress((void**)&pWcat, g_Wcat);
    cudaGetSymbolAddress((void**)&pF,    g_F);
    cudaGetSymbolAddress((void**)&pBias, g_bias);
    cudaGetSymbolAddress((void**)&pWhor, g_Whor);

    const int REC_SMEM = (St * Ht + Ht + 4 * Ht + St + St) * 4;   // ~142 KB
    cudaFuncSetAttribute(k_rec2,
                         cudaFuncAttributeMaxDynamicSharedMemorySize, REC_SMEM);

    const int SMEM_NN = (STG * TBM * ASTR + STG * TBK * BSTRN) * 4;   // 156672
    const int SMEM_NT = (STG * TBM * ASTR + STG * TBN * ASTR) * 4;    // 165888
    cudaFuncSetAttribute((const void*)k_tgemm2<false, false, false, true, false, true>,
                         cudaFuncAttributeMaxDynamicSharedMemorySize, SMEM_NN);
    cudaFuncSetAttribute((const void*)k_tgemm2<true, true, true, false, false, false>,
                         cudaFuncAttributeMaxDynamicSharedMemorySize, SMEM_NT);

    // prep
    k_transpose<<<dim3(16, 16), dim3(32, 32)>>>(W_hh);
    k_wcat_tail<<<(Vt * Ht + 255) / 256, 256>>>(W_c);
    k_roundW<<<(Vt * Ht + 255) / 256, 256>>>(W_ho);
    k_bias<<<Vt, 256>>>(W_c, b_ho, b_c);

    // U = emb[tok] @ W_ih^T + b_cell          (M=4096, N=512, K=512)  fp32 NT + gather
    k_sgemm<true, true, false, true><<<dim3(4, 32), 256>>>(
        emb, W_ih, pU, b_cell, target, Rt, Ht, Et, Et, Et, Ht);

    // M1 = W_c1 @ W_ho_r -> Wcat[:, 0:512]    (M=8000, N=512, K=8000) tf32 NN
    k_tgemm2<false, false, false, true, false, true><<<dim3(2, 63), 256, SMEM_NN>>>(
        W_c, pWhor, pWcat, nullptr, Vt, Ht, Vt, VHt, Ht, Ft);

    // sequential recurrence + attention -> g_F (tf32-rounded)
    k_rec2<<<Bt, Ht, REC_SMEM>>>(enc);

    // out = tanh(F @ Wcat^T + bias)           (M=4096, N=8000, K=1024) tf32 NT
    k_tgemm2<true, true, true, false, false, false><<<dim3(32, 32), 256, SMEM_NT>>>(
        pF, pWcat, out, pBias, Rt, Vt, Ft, Ft, Ft, Vt);
}